// round 7
// baseline (speedup 1.0000x reference)
#include <cuda_runtime.h>
#include <cstddef>

// Problem constants
#define Bn 8
#define Tn 512
#define Nn 64
#define Hn 256   // I == H == 256

// ---------------------------------------------------------------------------
// Scratch (device globals: allocation-free rule)
// ---------------------------------------------------------------------------
__device__ float g_xin[(size_t)Bn * Tn * Nn * Hn];   // per-layer input projections
__device__ float g_y0 [(size_t)Bn * Tn * Nn * Hn];   // layer-0 outputs
// hidden state, double buffered, K-MAJOR, n DUPLICATED:
//   g_h[buf][bnh][k=256][2*n + {0,1}]  (64 floats per k-row)
__device__ float g_h[2][Bn * 2 * 256 * 64];

// f32x2 packed helpers -------------------------------------------------------
__device__ __forceinline__ void fma2(unsigned long long& acc,
                                     unsigned long long a, unsigned long long b) {
    asm("fma.rn.f32x2 %0, %1, %2, %0;" : "+l"(acc) : "l"(a), "l"(b));
}
__device__ __forceinline__ void unpack2(unsigned long long v, float& lo, float& hi) {
    asm("mov.b64 {%0, %1}, %2;" : "=f"(lo), "=f"(hi) : "l"(v));
}

// ---------------------------------------------------------------------------
// Projection: g_xin[b, m, j] = sum_i X[b, m, i] * W[b, j, i] + b_ih[b,j] + b_hh[b,j]
//   (unchanged — known good)
// ---------------------------------------------------------------------------
__global__ __launch_bounds__(256) void proj_kernel(
    const float* __restrict__ Xext,
    const float* __restrict__ W,
    const float* __restrict__ bih,
    const float* __restrict__ bhh)
{
    __shared__ float Xs[64][33];
    __shared__ float Ws[64][33];

    const float* X = Xext ? Xext : g_y0;
    const int mt = blockIdx.x, jt = blockIdx.y, b = blockIdx.z;
    const int lin = threadIdx.x;
    const int tx = lin & 15, ty = lin >> 4;

    const float* Xb = X + ((size_t)b * (Tn * Nn) + mt * 64) * 256;
    const float* Wb = W + ((size_t)b * 256 + jt * 64) * 256;

    float acc[4][4] = {};

    for (int kk = 0; kk < 256; kk += 32) {
#pragma unroll
        for (int r = 0; r < 2; ++r) {
            int f   = lin + r * 256;
            int row = f >> 3;
            int kc  = (f & 7) << 2;
            float4 xv = *(const float4*)(Xb + (size_t)row * 256 + kk + kc);
            Xs[row][kc] = xv.x; Xs[row][kc + 1] = xv.y;
            Xs[row][kc + 2] = xv.z; Xs[row][kc + 3] = xv.w;
            float4 wv = *(const float4*)(Wb + (size_t)row * 256 + kk + kc);
            Ws[row][kc] = wv.x; Ws[row][kc + 1] = wv.y;
            Ws[row][kc + 2] = wv.z; Ws[row][kc + 3] = wv.w;
        }
        __syncthreads();
#pragma unroll
        for (int k = 0; k < 32; ++k) {
            float xv[4], wv[4];
#pragma unroll
            for (int i = 0; i < 4; ++i) xv[i] = Xs[ty * 4 + i][k];
#pragma unroll
            for (int j = 0; j < 4; ++j) wv[j] = Ws[tx + 16 * j][k];
#pragma unroll
            for (int i = 0; i < 4; ++i)
#pragma unroll
                for (int j = 0; j < 4; ++j)
                    acc[i][j] += xv[i] * wv[j];
        }
        __syncthreads();
    }

    const size_t mbase = (size_t)b * (Tn * Nn) + mt * 64 + ty * 4;
#pragma unroll
    for (int j = 0; j < 4; ++j) {
        int jg = jt * 64 + tx + 16 * j;
        float bias = bih[b * 256 + jg] + bhh[b * 256 + jg];
#pragma unroll
        for (int i = 0; i < 4; ++i)
            g_xin[(mbase + i) * 256 + jg] = acc[i][j] + bias;
    }
}

// ---------------------------------------------------------------------------
// Recurrence: 512 sequential steps, packed-f32x2 mainloop w/ pre-duplicated h.
//   128 CTAs = 16 clusters of 8. Cluster = (instance b, n-half nh) x 8 j-tiles.
//   Per-CTA tile: n=32 x j=32 x k=256. 128 threads, micro 2(n) x 4(j).
//   Per k: LDS.128 h (2 n, each dup'd -> 2 packed f32x2) + LDS.128 w (2 j-pairs)
//          + 4 FFMA2  = 6 issues / 8 FMA, no ALU in chain.
//   SMEM: w_s[256][36] (k-major, j-pair fast), h_s[256][68] (k-major, n dup'd).
// ---------------------------------------------------------------------------
__global__ __launch_bounds__(128) __cluster_dims__(8, 1, 1)
void rec_kernel(
    const float* __restrict__ hx,     // [B, L, N, H]
    const float* __restrict__ whh,    // [B, H, H]
    float* __restrict__ yext,         // layer outputs (nullptr -> g_y0)
    float* __restrict__ hn,           // [B, L, N, H] final hidden
    int layer)
{
    extern __shared__ float sm[];
    float* w_s = sm;                  // [256][36]  k-major, j fast
    float* h_s = sm + 256 * 36;       // [256][68]  k-major, 32 n dup'd (64) + pad

    const int jt  = blockIdx.x;
    const int bnh = blockIdx.y;             // b*2 + nh
    const int b   = bnh >> 1, nh = bnh & 1;
    const int lin = threadIdx.x;
    const int tx  = lin & 7,  ty = lin >> 3;   // tx: j-quad (0..7), ty: n-pair (0..15)
    const int tx4 = tx * 4,   ty2 = ty * 2,  ty4 = ty * 4;

    float* y = yext ? yext : g_y0;

    // Resident weight slice, transposed k-major: w_s[k][j] = whh[b][jt*32+j][k]
    const float* wb = whh + ((size_t)b * 256 + jt * 32) * 256;
    for (int f = lin; f < 2048; f += 128) {       // 2048 float4
        int j = f >> 6, kc = (f & 63) << 2;
        float4 v = *(const float4*)(wb + (size_t)j * 256 + kc);
        w_s[(kc + 0) * 36 + j] = v.x;
        w_s[(kc + 1) * 36 + j] = v.y;
        w_s[(kc + 2) * 36 + j] = v.z;
        w_s[(kc + 3) * 36 + j] = v.w;
    }

    // t=0: stage h from hx, transposed + duplicated (one-time)
    const float* h0 = hx + (size_t)(b * 2 + layer) * Nn * Hn + nh * 32 * 256;
    for (int f = lin; f < 8192; f += 128) {       // 32 n x 256 k scalars
        int n = f >> 8, k = f & 255;
        float v = h0[n * 256 + k];
        *(float2*)(h_s + k * 68 + 2 * n) = make_float2(v, v);
    }
    __syncthreads();

    const int jgbase = jt * 32 + tx4;
    const size_t hb_off = (size_t)bnh * 256 * 64;

    for (int t = 0; t < Tn; ++t) {
        const float* xt = g_xin + ((size_t)b * Tn + t) * (Nn * Hn) + nh * 32 * 256;
        float*       yt = y     + ((size_t)b * Tn + t) * (Nn * Hn) + nh * 32 * 256;
        float*     hdst = g_h[t & 1] + hb_off;

        // Prefetch xin[t] fragment before the GEMM so DRAM latency hides
        float4 x0 = __ldg((const float4*)(xt + (size_t)(ty2 + 0) * 256 + jgbase));
        float4 x1 = __ldg((const float4*)(xt + (size_t)(ty2 + 1) * 256 + jgbase));

        // Packed-f32x2 mainloop: acc[n][jpair]; h arrives pre-duplicated.
        unsigned long long a00 = 0ull, a01 = 0ull, a10 = 0ull, a11 = 0ull;
#pragma unroll 16
        for (int k = 0; k < 256; ++k) {
            ulonglong2 hv = *(const ulonglong2*)(h_s + k * 68 + ty4);
            ulonglong2 wv = *(const ulonglong2*)(w_s + k * 36 + tx4);
            fma2(a00, hv.x, wv.x);
            fma2(a01, hv.x, wv.y);
            fma2(a10, hv.y, wv.x);
            fma2(a11, hv.y, wv.y);
        }

        float f00, f01, f02, f03, f10, f11, f12, f13;
        unpack2(a00, f00, f01); unpack2(a01, f02, f03);
        unpack2(a10, f10, f11); unpack2(a11, f12, f13);

        float4 v0, v1;
        v0.x = tanhf(f00 + x0.x); v0.y = tanhf(f01 + x0.y);
        v0.z = tanhf(f02 + x0.z); v0.w = tanhf(f03 + x0.w);
        v1.x = tanhf(f10 + x1.x); v1.y = tanhf(f11 + x1.y);
        v1.z = tanhf(f12 + x1.z); v1.w = tanhf(f13 + x1.w);

        // h store first (k-major, duplicated) -> arrive -> y/hn -> wait
        *(float4*)(hdst + (size_t)(jgbase + 0) * 64 + ty4) = make_float4(v0.x, v0.x, v1.x, v1.x);
        *(float4*)(hdst + (size_t)(jgbase + 1) * 64 + ty4) = make_float4(v0.y, v0.y, v1.y, v1.y);
        *(float4*)(hdst + (size_t)(jgbase + 2) * 64 + ty4) = make_float4(v0.z, v0.z, v1.z, v1.z);
        *(float4*)(hdst + (size_t)(jgbase + 3) * 64 + ty4) = make_float4(v0.w, v0.w, v1.w, v1.w);

        asm volatile("barrier.cluster.arrive.aligned;" ::: "memory");

        *(float4*)(yt + (size_t)(ty2 + 0) * 256 + jgbase) = v0;
        *(float4*)(yt + (size_t)(ty2 + 1) * 256 + jgbase) = v1;
        if (t == Tn - 1) {
            float* hnp = hn + ((size_t)(b * 2 + layer) * Nn + nh * 32) * Hn;
            *(float4*)(hnp + (size_t)(ty2 + 0) * 256 + jgbase) = v0;
            *(float4*)(hnp + (size_t)(ty2 + 1) * 256 + jgbase) = v1;
        }

        asm volatile("barrier.cluster.wait.aligned;" ::: "memory");
        // aligned cluster barrier doubles as a CTA barrier; peer h stores visible.
        if (t < Tn - 1) {
            const float* hsrc = g_h[t & 1] + hb_off;
#pragma unroll 8
            for (int f = lin; f < 4096; f += 128) {   // 4096 float4 = 64 KB (dup'd)
                int k = f >> 4, nc = (f & 15) << 2;
                float4 v = __ldcg((const float4*)(hsrc + (size_t)k * 64 + nc));
                *(float4*)(h_s + k * 68 + nc) = v;
            }
            __syncthreads();
        }
    }
}

// ---------------------------------------------------------------------------
// Launch: 4 launches total (proj, rec) x 2 layers
// ---------------------------------------------------------------------------
extern "C" void kernel_launch(void* const* d_in, const int* in_sizes, int n_in,
                              void* d_out, int out_size)
{
    const float* x    = (const float*)d_in[0];
    const float* hx   = (const float*)d_in[1];
    const float* wih0 = (const float*)d_in[2];
    const float* whh0 = (const float*)d_in[3];
    const float* bih0 = (const float*)d_in[4];
    const float* bhh0 = (const float*)d_in[5];
    const float* wih1 = (const float*)d_in[6];
    const float* whh1 = (const float*)d_in[7];
    const float* bih1 = (const float*)d_in[8];
    const float* bhh1 = (const float*)d_in[9];

    float* out = (float*)d_out;                          // [B, T, N, H]
    float* hn  = out + (size_t)Bn * Tn * Nn * Hn;        // [B, L, N, H]

    const size_t rec_smem = (size_t)(256 * 36 + 256 * 68) * sizeof(float);  // 106496 B
    cudaFuncSetAttribute(rec_kernel, cudaFuncAttributeMaxDynamicSharedMemorySize,
                         (int)rec_smem);

    dim3 pgrid(Tn * Nn / 64, Hn / 64, Bn);   // (512, 4, 8)
    dim3 rgrid(8, Bn * 2);                    // 128 CTAs = 16 clusters of 8

    // Layer 0
    proj_kernel<<<pgrid, 256>>>(x, wih0, bih0, bhh0);
    rec_kernel<<<rgrid, 128, rec_smem>>>(hx, whh0, nullptr, hn, 0);

    // Layer 1
    proj_kernel<<<pgrid, 256>>>(nullptr, wih1, bih1, bhh1);
    rec_kernel<<<rgrid, 128, rec_smem>>>(hx, whh1, out, hn, 1);
}

// round 8
// speedup vs baseline: 2.1049x; 2.1049x over previous
#include <cuda_runtime.h>
#include <cstddef>

// Problem constants
#define Bn 8
#define Tn 512
#define Nn 64
#define Hn 256   // I == H == 256

// ---------------------------------------------------------------------------
// Scratch (device globals: allocation-free rule)
// ---------------------------------------------------------------------------
__device__ float g_xin[(size_t)Bn * Tn * Nn * Hn];   // per-layer input projections
__device__ float g_y0 [(size_t)Bn * Tn * Nn * Hn];   // layer-0 outputs
// hidden state, double buffered, K-MAJOR per n-half: [2][b*2+nh][k=256][n=32]
__device__ float g_h[2][Bn * 2 * 256 * 32];

// f32x2 packed helpers -------------------------------------------------------
__device__ __forceinline__ unsigned long long dup_f32(float x) {
    unsigned long long r;
    asm("mov.b64 %0, {%1, %1};" : "=l"(r) : "f"(x));
    return r;
}
__device__ __forceinline__ void fma2(unsigned long long& acc,
                                     unsigned long long a, unsigned long long b) {
    asm("fma.rn.f32x2 %0, %1, %2, %0;" : "+l"(acc) : "l"(a), "l"(b));
}
__device__ __forceinline__ void add2(unsigned long long& acc, unsigned long long v) {
    asm("add.rn.f32x2 %0, %0, %1;" : "+l"(acc) : "l"(v));
}
__device__ __forceinline__ void unpack2(unsigned long long v, float& lo, float& hi) {
    asm("mov.b64 {%0, %1}, %2;" : "=f"(lo), "=f"(hi) : "l"(v));
}

// ---------------------------------------------------------------------------
// Projection: g_xin[b, m, j] = sum_i X[b, m, i] * W[b, j, i] + b_ih[b,j] + b_hh[b,j]
//   (unchanged — known good)
// ---------------------------------------------------------------------------
__global__ __launch_bounds__(256) void proj_kernel(
    const float* __restrict__ Xext,
    const float* __restrict__ W,
    const float* __restrict__ bih,
    const float* __restrict__ bhh)
{
    __shared__ float Xs[64][33];
    __shared__ float Ws[64][33];

    const float* X = Xext ? Xext : g_y0;
    const int mt = blockIdx.x, jt = blockIdx.y, b = blockIdx.z;
    const int lin = threadIdx.x;
    const int tx = lin & 15, ty = lin >> 4;

    const float* Xb = X + ((size_t)b * (Tn * Nn) + mt * 64) * 256;
    const float* Wb = W + ((size_t)b * 256 + jt * 64) * 256;

    float acc[4][4] = {};

    for (int kk = 0; kk < 256; kk += 32) {
#pragma unroll
        for (int r = 0; r < 2; ++r) {
            int f   = lin + r * 256;
            int row = f >> 3;
            int kc  = (f & 7) << 2;
            float4 xv = *(const float4*)(Xb + (size_t)row * 256 + kk + kc);
            Xs[row][kc] = xv.x; Xs[row][kc + 1] = xv.y;
            Xs[row][kc + 2] = xv.z; Xs[row][kc + 3] = xv.w;
            float4 wv = *(const float4*)(Wb + (size_t)row * 256 + kk + kc);
            Ws[row][kc] = wv.x; Ws[row][kc + 1] = wv.y;
            Ws[row][kc + 2] = wv.z; Ws[row][kc + 3] = wv.w;
        }
        __syncthreads();
#pragma unroll
        for (int k = 0; k < 32; ++k) {
            float xv[4], wv[4];
#pragma unroll
            for (int i = 0; i < 4; ++i) xv[i] = Xs[ty * 4 + i][k];
#pragma unroll
            for (int j = 0; j < 4; ++j) wv[j] = Ws[tx + 16 * j][k];
#pragma unroll
            for (int i = 0; i < 4; ++i)
#pragma unroll
                for (int j = 0; j < 4; ++j)
                    acc[i][j] += xv[i] * wv[j];
        }
        __syncthreads();
    }

    const size_t mbase = (size_t)b * (Tn * Nn) + mt * 64 + ty * 4;
#pragma unroll
    for (int j = 0; j < 4; ++j) {
        int jg = jt * 64 + tx + 16 * j;
        float bias = bih[b * 256 + jg] + bhh[b * 256 + jg];
#pragma unroll
        for (int i = 0; i < 4; ++i)
            g_xin[(mbase + i) * 256 + jg] = acc[i][j] + bias;
    }
}

// ---------------------------------------------------------------------------
// Recurrence: 512 sequential steps. R6 mainloop + k-split over 256 threads.
//   128 CTAs = 16 clusters of 8. Cluster = (instance b, n-half nh) x 8 j-tiles.
//   Per-CTA tile: n=32 x j=32 x k=256. 256 threads:
//     kh = lin>>7 selects k-half [kh*128, kh*128+128); within half,
//     micro 2(n) x 4(j): per k = LDS.64 h + LDS.128 w + 2 dup + 4 FFMA2.
//   2 warps/SMSP -> LDS latency covered by the sibling warp.
//   SMEM: w_s[256][36], h_s[256][36] (k-major), red[128][4] ull scratch.
// ---------------------------------------------------------------------------
__global__ __launch_bounds__(256) __cluster_dims__(8, 1, 1)
void rec_kernel(
    const float* __restrict__ hx,     // [B, L, N, H]
    const float* __restrict__ whh,    // [B, H, H]
    float* __restrict__ yext,         // layer outputs (nullptr -> g_y0)
    float* __restrict__ hn,           // [B, L, N, H] final hidden
    int layer)
{
    extern __shared__ float sm[];
    float* w_s = sm;                  // [256][36]  k-major, j fast
    float* h_s = sm + 256 * 36;       // [256][36]  k-major, n fast (32 + pad)
    unsigned long long* red =
        (unsigned long long*)(sm + 2 * 256 * 36);   // [128][4]

    const int jt  = blockIdx.x;
    const int bnh = blockIdx.y;             // b*2 + nh
    const int b   = bnh >> 1, nh = bnh & 1;
    const int lin = threadIdx.x;
    const int kh  = lin >> 7;               // k-half: 0 or 1 (warp-uniform)
    const int wl  = lin & 127;
    const int tx  = wl & 7,  ty = wl >> 3;  // tx: j-quad (0..7), ty: n-pair (0..15)
    const int tx4 = tx * 4,  ty2 = ty * 2;
    const int kbeg = kh << 7;               // 0 or 128

    float* y = yext ? yext : g_y0;

    // Resident weight slice, transposed k-major: w_s[k][j] = whh[b][jt*32+j][k]
    const float* wb = whh + ((size_t)b * 256 + jt * 32) * 256;
    for (int f = lin; f < 2048; f += 256) {       // 2048 float4
        int j = f >> 6, kc = (f & 63) << 2;
        float4 v = *(const float4*)(wb + (size_t)j * 256 + kc);
        w_s[(kc + 0) * 36 + j] = v.x;
        w_s[(kc + 1) * 36 + j] = v.y;
        w_s[(kc + 2) * 36 + j] = v.z;
        w_s[(kc + 3) * 36 + j] = v.w;
    }

    // t=0: stage h from hx with on-the-fly transpose (one-time)
    const float* h0 = hx + (size_t)(b * 2 + layer) * Nn * Hn + nh * 32 * 256;
    for (int f = lin; f < 8192; f += 256) {       // 32 n x 256 k scalars
        int n = f >> 8, k = f & 255;
        h_s[k * 36 + n] = h0[n * 256 + k];
    }
    __syncthreads();

    const int jgbase = jt * 32 + tx4;
    const size_t hb_off = (size_t)bnh * 256 * 32;

    for (int t = 0; t < Tn; ++t) {
        const float* xt = g_xin + ((size_t)b * Tn + t) * (Nn * Hn) + nh * 32 * 256;
        float*       yt = y     + ((size_t)b * Tn + t) * (Nn * Hn) + nh * 32 * 256;
        float*     hdst = g_h[t & 1] + hb_off;

        // Prefetch xin[t] fragment (lower half only, it owns the epilogue)
        float4 x0, x1;
        if (!kh) {
            x0 = __ldg((const float4*)(xt + (size_t)(ty2 + 0) * 256 + jgbase));
            x1 = __ldg((const float4*)(xt + (size_t)(ty2 + 1) * 256 + jgbase));
        }

        // Packed-f32x2 mainloop over this thread's k-half
        unsigned long long a00 = 0ull, a01 = 0ull, a10 = 0ull, a11 = 0ull;
#pragma unroll 8
        for (int k = kbeg; k < kbeg + 128; ++k) {
            float2 hv = *(const float2*)(h_s + k * 36 + ty2);
            ulonglong2 wv = *(const ulonglong2*)(w_s + k * 36 + tx4);
            unsigned long long h0d = dup_f32(hv.x);
            unsigned long long h1d = dup_f32(hv.y);
            fma2(a00, h0d, wv.x);
            fma2(a01, h0d, wv.y);
            fma2(a10, h1d, wv.x);
            fma2(a11, h1d, wv.y);
        }

        // Cross-half reduction through SMEM scratch
        if (kh) {
            ulonglong2* r = (ulonglong2*)(red + (size_t)wl * 4);
            r[0] = make_ulonglong2(a00, a01);
            r[1] = make_ulonglong2(a10, a11);
        }
        __syncthreads();

        float4 v0, v1;
        if (!kh) {
            const ulonglong2* r = (const ulonglong2*)(red + (size_t)wl * 4);
            ulonglong2 p0 = r[0], p1 = r[1];
            add2(a00, p0.x); add2(a01, p0.y);
            add2(a10, p1.x); add2(a11, p1.y);

            float f00, f01, f02, f03, f10, f11, f12, f13;
            unpack2(a00, f00, f01); unpack2(a01, f02, f03);
            unpack2(a10, f10, f11); unpack2(a11, f12, f13);

            v0.x = tanhf(f00 + x0.x); v0.y = tanhf(f01 + x0.y);
            v0.z = tanhf(f02 + x0.z); v0.w = tanhf(f03 + x0.w);
            v1.x = tanhf(f10 + x1.x); v1.y = tanhf(f11 + x1.y);
            v1.z = tanhf(f12 + x1.z); v1.w = tanhf(f13 + x1.w);

            // h store first (k-major: hdst[jg][n_local])
            *(float2*)(hdst + (size_t)(jgbase + 0) * 32 + ty2) = make_float2(v0.x, v1.x);
            *(float2*)(hdst + (size_t)(jgbase + 1) * 32 + ty2) = make_float2(v0.y, v1.y);
            *(float2*)(hdst + (size_t)(jgbase + 2) * 32 + ty2) = make_float2(v0.z, v1.z);
            *(float2*)(hdst + (size_t)(jgbase + 3) * 32 + ty2) = make_float2(v0.w, v1.w);
        }

        asm volatile("barrier.cluster.arrive.aligned;" ::: "memory");

        if (!kh) {
            *(float4*)(yt + (size_t)(ty2 + 0) * 256 + jgbase) = v0;
            *(float4*)(yt + (size_t)(ty2 + 1) * 256 + jgbase) = v1;
            if (t == Tn - 1) {
                float* hnp = hn + ((size_t)(b * 2 + layer) * Nn + nh * 32) * Hn;
                *(float4*)(hnp + (size_t)(ty2 + 0) * 256 + jgbase) = v0;
                *(float4*)(hnp + (size_t)(ty2 + 1) * 256 + jgbase) = v1;
            }
        }

        asm volatile("barrier.cluster.wait.aligned;" ::: "memory");
        // aligned cluster barrier doubles as a CTA barrier; peer h stores visible.
        if (t < Tn - 1) {
            const float* hsrc = g_h[t & 1] + hb_off;
#pragma unroll 8
            for (int f = lin; f < 2048; f += 256) {   // 2048 float4 = 32 KB
                int k = f >> 3, nc = (f & 7) << 2;
                float4 v = __ldcg((const float4*)(hsrc + (size_t)k * 32 + nc));
                *(float4*)(h_s + k * 36 + nc) = v;
            }
            __syncthreads();
        }
    }
}

// ---------------------------------------------------------------------------
// Launch: 4 launches total (proj, rec) x 2 layers
// ---------------------------------------------------------------------------
extern "C" void kernel_launch(void* const* d_in, const int* in_sizes, int n_in,
                              void* d_out, int out_size)
{
    const float* x    = (const float*)d_in[0];
    const float* hx   = (const float*)d_in[1];
    const float* wih0 = (const float*)d_in[2];
    const float* whh0 = (const float*)d_in[3];
    const float* bih0 = (const float*)d_in[4];
    const float* bhh0 = (const float*)d_in[5];
    const float* wih1 = (const float*)d_in[6];
    const float* whh1 = (const float*)d_in[7];
    const float* bih1 = (const float*)d_in[8];
    const float* bhh1 = (const float*)d_in[9];

    float* out = (float*)d_out;                          // [B, T, N, H]
    float* hn  = out + (size_t)Bn * Tn * Nn * Hn;        // [B, L, N, H]

    // w_s + h_s + reduction scratch
    const size_t rec_smem = (size_t)(2 * 256 * 36) * sizeof(float)
                          + 128 * 4 * sizeof(unsigned long long);   // 77824 B
    cudaFuncSetAttribute(rec_kernel, cudaFuncAttributeMaxDynamicSharedMemorySize,
                         (int)rec_smem);

    dim3 pgrid(Tn * Nn / 64, Hn / 64, Bn);   // (512, 4, 8)
    dim3 rgrid(8, Bn * 2);                    // 128 CTAs = 16 clusters of 8

    // Layer 0
    proj_kernel<<<pgrid, 256>>>(x, wih0, bih0, bhh0);
    rec_kernel<<<rgrid, 256, rec_smem>>>(hx, whh0, nullptr, hn, 0);

    // Layer 1
    proj_kernel<<<pgrid, 256>>>(nullptr, wih1, bih1, bhh1);
    rec_kernel<<<rgrid, 256, rec_smem>>>(hx, whh1, out, hn, 1);
}

// round 10
// speedup vs baseline: 3.2516x; 1.5448x over previous
#include <cuda_runtime.h>
#include <cstddef>
#include <cstdint>

// Problem constants
#define Bn 8
#define Tn 512
#define Nn 64
#define Hn 256   // I == H == 256

// ---------------------------------------------------------------------------
// Scratch (device globals: allocation-free rule)
// ---------------------------------------------------------------------------
__device__ float g_xin[(size_t)Bn * Tn * Nn * Hn];   // per-layer input projections
__device__ float g_y0 [(size_t)Bn * Tn * Nn * Hn];   // layer-0 outputs

// f32x2 packed helpers -------------------------------------------------------
__device__ __forceinline__ unsigned long long dup_f32(float x) {
    unsigned long long r;
    asm("mov.b64 %0, {%1, %1};" : "=l"(r) : "f"(x));
    return r;
}
__device__ __forceinline__ void fma2(unsigned long long& acc,
                                     unsigned long long a, unsigned long long b) {
    asm("fma.rn.f32x2 %0, %1, %2, %0;" : "+l"(acc) : "l"(a), "l"(b));
}
__device__ __forceinline__ void add2(unsigned long long& acc, unsigned long long v) {
    asm("add.rn.f32x2 %0, %0, %1;" : "+l"(acc) : "l"(v));
}
__device__ __forceinline__ void unpack2(unsigned long long v, float& lo, float& hi) {
    asm("mov.b64 {%0, %1}, %2;" : "=f"(lo), "=f"(hi) : "l"(v));
}
__device__ __forceinline__ unsigned long long pack2(float lo, float hi) {
    unsigned long long r;
    asm("mov.b64 %0, {%1, %2};" : "=l"(r) : "f"(lo), "f"(hi));
    return r;
}
__device__ __forceinline__ uint32_t smem_u32(const void* p) {
    uint32_t a;
    asm("{ .reg .u64 t; cvta.to.shared.u64 t, %1; cvt.u32.u64 %0, t; }"
        : "=r"(a) : "l"(p));
    return a;
}

// ---------------------------------------------------------------------------
// Projection: g_xin[b, m, j] = sum_i X[b, m, i] * W[b, j, i] + b_ih[b,j] + b_hh[b,j]
//   (unchanged — known good)
// ---------------------------------------------------------------------------
__global__ __launch_bounds__(256) void proj_kernel(
    const float* __restrict__ Xext,
    const float* __restrict__ W,
    const float* __restrict__ bih,
    const float* __restrict__ bhh)
{
    __shared__ float Xs[64][33];
    __shared__ float Ws[64][33];

    const float* X = Xext ? Xext : g_y0;
    const int mt = blockIdx.x, jt = blockIdx.y, b = blockIdx.z;
    const int lin = threadIdx.x;
    const int tx = lin & 15, ty = lin >> 4;

    const float* Xb = X + ((size_t)b * (Tn * Nn) + mt * 64) * 256;
    const float* Wb = W + ((size_t)b * 256 + jt * 64) * 256;

    float acc[4][4] = {};

    for (int kk = 0; kk < 256; kk += 32) {
#pragma unroll
        for (int r = 0; r < 2; ++r) {
            int f   = lin + r * 256;
            int row = f >> 3;
            int kc  = (f & 7) << 2;
            float4 xv = *(const float4*)(Xb + (size_t)row * 256 + kk + kc);
            Xs[row][kc] = xv.x; Xs[row][kc + 1] = xv.y;
            Xs[row][kc + 2] = xv.z; Xs[row][kc + 3] = xv.w;
            float4 wv = *(const float4*)(Wb + (size_t)row * 256 + kk + kc);
            Ws[row][kc] = wv.x; Ws[row][kc + 1] = wv.y;
            Ws[row][kc + 2] = wv.z; Ws[row][kc + 3] = wv.w;
        }
        __syncthreads();
#pragma unroll
        for (int k = 0; k < 32; ++k) {
            float xv[4], wv[4];
#pragma unroll
            for (int i = 0; i < 4; ++i) xv[i] = Xs[ty * 4 + i][k];
#pragma unroll
            for (int j = 0; j < 4; ++j) wv[j] = Ws[tx + 16 * j][k];
#pragma unroll
            for (int i = 0; i < 4; ++i)
#pragma unroll
                for (int j = 0; j < 4; ++j)
                    acc[i][j] += xv[i] * wv[j];
        }
        __syncthreads();
    }

    const size_t mbase = (size_t)b * (Tn * Nn) + mt * 64 + ty * 4;
#pragma unroll
    for (int j = 0; j < 4; ++j) {
        int jg = jt * 64 + tx + 16 * j;
        float bias = bih[b * 256 + jg] + bhh[b * 256 + jg];
#pragma unroll
        for (int i = 0; i < 4; ++i)
            g_xin[(mbase + i) * 256 + jg] = acc[i][j] + bias;
    }
}

// ---------------------------------------------------------------------------
// Recurrence: 512 sequential steps. Sample rows are INDEPENDENT across n, so:
//   64 clusters of 2 CTAs. Cluster = (instance b, n-octet). CTA = j-half (128 j).
//   Per-CTA: 8n x 128j x 256k per step; W half (128x256 f32) resident in SMEM.
//   h lives in SMEM (double-buffered [2][256][10]); per step each CTA writes its
//   8n x 128j half locally AND into the peer via DSMEM (st.shared::cluster).
//   256 threads, k-split: kh=lin>>7 does k in [kh*128, kh*128+128).
//   Thread micro: 2n x 4j. Per k: LDS.64 h + LDS.128 w + 2 dup + 4 FFMA2.
// ---------------------------------------------------------------------------
#define WP 132   // w_s row stride (floats)
#define HP 10    // h_buf row stride (floats)

__global__ __launch_bounds__(256) __cluster_dims__(2, 1, 1)
void rec_kernel(
    const float* __restrict__ hx,     // [B, L, N, H]
    const float* __restrict__ whh,    // [B, H, H]
    float* __restrict__ yext,         // layer outputs (nullptr -> g_y0)
    float* __restrict__ hn,           // [B, L, N, H] final hidden
    int layer)
{
    extern __shared__ float sm[];
    float* w_s  = sm;                       // [256][WP]  k-major, j-half fast
    float* hbuf = sm + 256 * WP;            // [2][256][HP] k = GLOBAL j index
    unsigned long long* red =
        (unsigned long long*)(sm + 256 * WP + 2 * 256 * HP);  // [128][4]

    const int jh  = blockIdx.x;             // j-half = cluster rank (0/1)
    const int bn  = blockIdx.y;             // b*8 + n-octet
    const int b   = bn >> 3, nch = bn & 7;
    const int lin = threadIdx.x;
    const int kh  = lin >> 7;               // k-half (warp-uniform)
    const int wl  = lin & 127;
    const int jc  = wl >> 5;                // j-chunk of 32 within half (0..3)
    const int lane = wl & 31;
    const int q   = lane & 7;               // j-quad (0..7)
    const int p   = lane >> 3;              // n-pair (0..3)
    const int jl  = jc * 32 + q * 4;        // j within half (0..124)
    const int p2  = p * 2;
    const int kbeg = kh << 7;

    float* y = yext ? yext : g_y0;

    // Resident W half, transposed k-major: w_s[k][j] = whh[b][jh*128+j][k]
    const float* wb = whh + ((size_t)b * 256 + jh * 128) * 256;
    for (int f = lin; f < 8192; f += 256) {       // 128 j x 64 float4
        int j = f >> 6, kc = (f & 63) << 2;
        float4 v = *(const float4*)(wb + (size_t)j * 256 + kc);
        w_s[(kc + 0) * WP + j] = v.x;
        w_s[(kc + 1) * WP + j] = v.y;
        w_s[(kc + 2) * WP + j] = v.z;
        w_s[(kc + 3) * WP + j] = v.w;
    }

    // t=0 h staging: full 256-k rows for our 8 n, transposed into hbuf[1]
    const float* h0 = hx + (size_t)(b * 2 + layer) * Nn * Hn + (size_t)nch * 8 * Hn;
    for (int f = lin; f < 2048; f += 256) {       // 8 n x 256 k scalars
        int n = f >> 8, k = f & 255;
        hbuf[(size_t)(256 + k) * HP + n] = h0[n * 256 + k];   // buffer 1
    }
    __syncthreads();

    // Peer DSMEM base for hbuf
    const uint32_t hbuf_local = smem_u32(hbuf);
    uint32_t hbuf_peer;
    asm("mapa.shared::cluster.u32 %0, %1, %2;"
        : "=r"(hbuf_peer) : "r"(hbuf_local), "r"(jh ^ 1));

    const int jrow0 = jh * 128 + jl;        // global j row base for our outputs
    const size_t xybase0 = (size_t)nch * 8 * Hn + jh * 128 + jl;

    for (int t = 0; t < Tn; ++t) {
        const float* hcur = hbuf + (size_t)(((t + 1) & 1) * 256) * HP;

        // Prefetch xin[t] fragment (lower half owns the epilogue)
        const size_t tb = ((size_t)b * Tn + t) * (Nn * Hn) + xybase0;
        float4 x0, x1;
        if (!kh) {
            x0 = __ldg((const float4*)(g_xin + tb + (size_t)(p2 + 0) * Hn));
            x1 = __ldg((const float4*)(g_xin + tb + (size_t)(p2 + 1) * Hn));
        }

        // Packed-f32x2 mainloop over this thread's k-half
        unsigned long long a00 = 0ull, a01 = 0ull, a10 = 0ull, a11 = 0ull;
#pragma unroll 8
        for (int k = kbeg; k < kbeg + 128; ++k) {
            float2 hv = *(const float2*)(hcur + (size_t)k * HP + p2);
            ulonglong2 wv = *(const ulonglong2*)(w_s + (size_t)k * WP + jl);
            unsigned long long h0d = dup_f32(hv.x);
            unsigned long long h1d = dup_f32(hv.y);
            fma2(a00, h0d, wv.x);
            fma2(a01, h0d, wv.y);
            fma2(a10, h1d, wv.x);
            fma2(a11, h1d, wv.y);
        }

        // Cross-half reduction through SMEM scratch
        if (kh) {
            ulonglong2* r = (ulonglong2*)(red + (size_t)wl * 4);
            r[0] = make_ulonglong2(a00, a01);
            r[1] = make_ulonglong2(a10, a11);
        }
        __syncthreads();

        if (!kh) {
            const ulonglong2* r = (const ulonglong2*)(red + (size_t)wl * 4);
            ulonglong2 q0 = r[0], q1 = r[1];
            add2(a00, q0.x); add2(a01, q0.y);
            add2(a10, q1.x); add2(a11, q1.y);

            float f00, f01, f02, f03, f10, f11, f12, f13;
            unpack2(a00, f00, f01); unpack2(a01, f02, f03);
            unpack2(a10, f10, f11); unpack2(a11, f12, f13);

            float4 v0, v1;
            v0.x = tanhf(f00 + x0.x); v0.y = tanhf(f01 + x0.y);
            v0.z = tanhf(f02 + x0.z); v0.w = tanhf(f03 + x0.w);
            v1.x = tanhf(f10 + x1.x); v1.y = tanhf(f11 + x1.y);
            v1.z = tanhf(f12 + x1.z); v1.w = tanhf(f13 + x1.w);

            // y (and hn) global stores
            float* yt = y + ((size_t)b * Tn + t) * (Nn * Hn) + xybase0;
            *(float4*)(yt + (size_t)(p2 + 0) * Hn) = v0;
            *(float4*)(yt + (size_t)(p2 + 1) * Hn) = v1;
            if (t == Tn - 1) {
                float* hnp = hn + (size_t)(b * 2 + layer) * Nn * Hn + xybase0;
                *(float4*)(hnp + (size_t)(p2 + 0) * Hn) = v0;
                *(float4*)(hnp + (size_t)(p2 + 1) * Hn) = v1;
            }

            // h stores: local + peer DSMEM, rows = global j, cols = local n-pair
            const int boff = (t & 1) * 256;
            float* hl = hbuf + (size_t)(boff + jrow0) * HP + p2;
            const uint32_t rbase = hbuf_peer
                + (uint32_t)(((boff + jrow0) * HP + p2) * sizeof(float));
            unsigned long long pk;

            *(float2*)(hl + 0 * HP) = make_float2(v0.x, v1.x);
            pk = pack2(v0.x, v1.x);
            asm volatile("st.shared::cluster.b64 [%0], %1;"
                         :: "r"(rbase + 0 * HP * 4), "l"(pk));
            *(float2*)(hl + 1 * HP) = make_float2(v0.y, v1.y);
            pk = pack2(v0.y, v1.y);
            asm volatile("st.shared::cluster.b64 [%0], %1;"
                         :: "r"(rbase + 1 * HP * 4), "l"(pk));
            *(float2*)(hl + 2 * HP) = make_float2(v0.z, v1.z);
            pk = pack2(v0.z, v1.z);
            asm volatile("st.shared::cluster.b64 [%0], %1;"
                         :: "r"(rbase + 2 * HP * 4), "l"(pk));
            *(float2*)(hl + 3 * HP) = make_float2(v0.w, v1.w);
            pk = pack2(v0.w, v1.w);
            asm volatile("st.shared::cluster.b64 [%0], %1;"
                         :: "r"(rbase + 3 * HP * 4), "l"(pk));
        }

        // 2-CTA cluster barrier: orders all shared::cluster stores, acts as
        // CTA barrier too (aligned, all threads).
        asm volatile("barrier.cluster.arrive.aligned;" ::: "memory");
        asm volatile("barrier.cluster.wait.aligned;"   ::: "memory");
    }
}

// ---------------------------------------------------------------------------
// Launch: 4 launches total (proj, rec) x 2 layers
// ---------------------------------------------------------------------------
extern "C" void kernel_launch(void* const* d_in, const int* in_sizes, int n_in,
                              void* d_out, int out_size)
{
    const float* x    = (const float*)d_in[0];
    const float* hx   = (const float*)d_in[1];
    const float* wih0 = (const float*)d_in[2];
    const float* whh0 = (const float*)d_in[3];
    const float* bih0 = (const float*)d_in[4];
    const float* bhh0 = (const float*)d_in[5];
    const float* wih1 = (const float*)d_in[6];
    const float* whh1 = (const float*)d_in[7];
    const float* bih1 = (const float*)d_in[8];
    const float* bhh1 = (const float*)d_in[9];

    float* out = (float*)d_out;                          // [B, T, N, H]
    float* hn  = out + (size_t)Bn * Tn * Nn * Hn;        // [B, L, N, H]

    // w_s[256][132] + hbuf[2][256][10] + red[128][4] ull
    const size_t rec_smem = (size_t)(256 * WP + 2 * 256 * HP) * sizeof(float)
                          + 128 * 4 * sizeof(unsigned long long);   // 159744 B
    cudaFuncSetAttribute(rec_kernel, cudaFuncAttributeMaxDynamicSharedMemorySize,
                         (int)rec_smem);

    dim3 pgrid(Tn * Nn / 64, Hn / 64, Bn);   // (512, 4, 8)
    dim3 rgrid(2, Bn * 8);                    // 128 CTAs = 64 clusters of 2

    // Layer 0
    proj_kernel<<<pgrid, 256>>>(x, wih0, bih0, bhh0);
    rec_kernel<<<rgrid, 256, rec_smem>>>(hx, whh0, nullptr, hn, 0);

    // Layer 1
    proj_kernel<<<pgrid, 256>>>(nullptr, wih1, bih1, bhh1);
    rec_kernel<<<rgrid, 256, rec_smem>>>(hx, whh1, out, hn, 1);
}